// round 8
// baseline (speedup 1.0000x reference)
#include <cuda_runtime.h>
#include <cuda_bf16.h>
#include <math.h>
#include <stdint.h>

#define LSEQ   4096
#define HIDDEN 4096
#define NH     32
#define NKV    8
#define HD     128
#define CHUNKS 128
#define NC     32
#define QDIM   4096   // NH*HD
#define KVDIM  1024   // NKV*HD

// single dynamic smem declaration for ALL kernels
extern __shared__ __align__(1024) unsigned char dyn_smem[];

// ---------------- scratch (static device globals; no allocation) ----------------
__device__ float g_q[(size_t)LSEQ * QDIM];
__device__ float g_k[(size_t)LSEQ * KVDIM];
__device__ float g_v[(size_t)LSEQ * KVDIM];
__device__ float g_gate[(size_t)LSEQ * QDIM];
__device__ float g_y[(size_t)LSEQ * QDIM];
__device__ float g_dt[LSEQ * NH];
__device__ float g_G[LSEQ * NH];
__device__ float g_cdec[NC * NH];
__device__ float g_cs[(size_t)NC * NH * HD * HD];
__device__ float g_prev[(size_t)NC * NH * HD * HD];

// ---------------- helpers ----------------
__device__ __forceinline__ unsigned pack_bf2(float a, float b) {
    __nv_bfloat162 t = __floats2bfloat162_rn(a, b);
    return reinterpret_cast<unsigned&>(t);
}
__device__ __forceinline__ uint32_t f2tf(float x) {
    uint32_t u;
    asm("cvt.rna.tf32.f32 %0, %1;" : "=r"(u) : "f"(x));
    return u;
}
__device__ __forceinline__ void tf_store(uint32_t* hi, uint32_t* lo, int idx, float x) {
    uint32_t h = f2tf(x);
    hi[idx] = h;
    lo[idx] = f2tf(x - __uint_as_float(h));
}
// fragment-permuted indices for m16n8k8 tf32 (formulas verified on-chip in round 2)
__device__ __forceinline__ int aidx(int m, int k) {
    return (((k >> 3) * 8 + (m >> 4)) * 32 + (m & 7) * 4 + (k & 3)) * 4
           + ((m >> 3) & 1) + (((k >> 2) & 1) << 1);
}
__device__ __forceinline__ int bidx(int n, int k) {
    return (((k >> 3) * 16 + (n >> 3)) * 32 + (n & 7) * 4 + (k & 3)) * 2
           + ((k >> 2) & 1);
}
__device__ __forceinline__ void mma_tf32(float* c, const uint32_t* a, uint32_t b0, uint32_t b1) {
    asm volatile("mma.sync.aligned.m16n8k8.row.col.f32.tf32.tf32.f32 "
                 "{%0,%1,%2,%3}, {%4,%5,%6,%7}, {%8,%9}, {%0,%1,%2,%3};"
                 : "+f"(c[0]), "+f"(c[1]), "+f"(c[2]), "+f"(c[3])
                 : "r"(a[0]), "r"(a[1]), "r"(a[2]), "r"(a[3]), "r"(b0), "r"(b1));
}

// ---------------- bf16x3 tensor-core GEMM (round-3 version, in-kernel split) ----------------
// C[M,N] = A[M,K] @ B[N,K]^T, fp32 acc, MMAs: hh + hl + lh (m16n8k16 bf16).
__global__ void __launch_bounds__(256, 1) gemm_bf16x3(const float* __restrict__ A,
                                                      const float* __restrict__ B,
                                                      float* __restrict__ C,
                                                      int M, int N, int K) {
    unsigned* smem_u = (unsigned*)dyn_smem;
    const int tid = threadIdx.x;
    const int warp = tid >> 5, lane = tid & 31;
    const int wm = warp >> 2, wn = warp & 3;
    const int bm = blockIdx.y * 128, bn = blockIdx.x * 128;

    float acc[4][4][4];
#pragma unroll
    for (int a = 0; a < 4; a++)
#pragma unroll
        for (int b = 0; b < 4; b++)
#pragma unroll
            for (int c = 0; c < 4; c++) acc[a][b][c] = 0.f;

    const float* a_g[4];
    const float* b_g[4];
    int a_st[4], b_st[4];
#pragma unroll
    for (int i = 0; i < 4; i++) {
        const int idx = tid + i * 256;
        const int row = idx >> 3, c4 = idx & 7;
        const int k0 = c4 * 4;
        const int ks = k0 >> 4, ki = k0 & 15;
        a_g[i] = A + (size_t)(bm + row) * K + k0;
        b_g[i] = B + (size_t)(bn + row) * K + k0;
        const int ri = row & 15, tm = row >> 4;
        const int laneA = (ri & 7) * 4 + ((ki & 7) >> 1);
        const int regA = (ri >> 3) + ((ki >> 3) << 1);
        a_st[i] = ((ks * 8 + tm) * 32 + laneA) * 4 + regA;
        const int ci = row & 7, tn = row >> 3;
        const int laneB = ci * 4 + ((ki & 7) >> 1);
        const int regB = ki >> 3;
        b_st[i] = ((ks * 16 + tn) * 32 + laneB) * 2 + regB;
    }

    float4 ar[4], br[4];
#pragma unroll
    for (int i = 0; i < 4; i++) {
        ar[i] = *(const float4*)(a_g[i]);
        br[i] = *(const float4*)(b_g[i]);
    }

    auto store_tiles = [&](unsigned* base) {
        unsigned* Ah = base;
        unsigned* Al = base + 2048;
        unsigned* Bh = base + 4096;
        unsigned* Bl = base + 6144;
#pragma unroll
        for (int i = 0; i < 4; i++) {
            {
                float4 v = ar[i];
                __nv_bfloat162 h01 = __floats2bfloat162_rn(v.x, v.y);
                __nv_bfloat162 h23 = __floats2bfloat162_rn(v.z, v.w);
                float2 f01 = __bfloat1622float2(h01);
                float2 f23 = __bfloat1622float2(h23);
                Ah[a_st[i]]     = reinterpret_cast<unsigned&>(h01);
                Ah[a_st[i] + 4] = reinterpret_cast<unsigned&>(h23);
                Al[a_st[i]]     = pack_bf2(v.x - f01.x, v.y - f01.y);
                Al[a_st[i] + 4] = pack_bf2(v.z - f23.x, v.w - f23.y);
            }
            {
                float4 v = br[i];
                __nv_bfloat162 h01 = __floats2bfloat162_rn(v.x, v.y);
                __nv_bfloat162 h23 = __floats2bfloat162_rn(v.z, v.w);
                float2 f01 = __bfloat1622float2(h01);
                float2 f23 = __bfloat1622float2(h23);
                Bh[b_st[i]]     = reinterpret_cast<unsigned&>(h01);
                Bh[b_st[i] + 2] = reinterpret_cast<unsigned&>(h23);
                Bl[b_st[i]]     = pack_bf2(v.x - f01.x, v.y - f01.y);
                Bl[b_st[i] + 2] = pack_bf2(v.z - f23.x, v.w - f23.y);
            }
        }
    };

    store_tiles(smem_u);
    __syncthreads();

    const int nk = K >> 5;
    for (int kb = 0; kb < nk; kb++) {
        const int cur = kb & 1;
        const bool has_next = (kb + 1) < nk;
        if (has_next) {
            const int off = (kb + 1) * 32;
#pragma unroll
            for (int i = 0; i < 4; i++) {
                ar[i] = *(const float4*)(a_g[i] + off);
                br[i] = *(const float4*)(b_g[i] + off);
            }
        }
        const unsigned* base = smem_u + cur * 8192;
        const unsigned* Ahb = base;
        const unsigned* Alb = base + 2048;
        const unsigned* Bhb = base + 4096;
        const unsigned* Blb = base + 6144;
#pragma unroll
        for (int ks = 0; ks < 2; ks++) {
            unsigned bh[4][2], bl[4][2];
#pragma unroll
            for (int nt = 0; nt < 4; nt++) {
                const int tn = wn * 4 + nt;
                uint2 vh = *(const uint2*)(Bhb + ((ks * 16 + tn) * 32 + lane) * 2);
                uint2 vl = *(const uint2*)(Blb + ((ks * 16 + tn) * 32 + lane) * 2);
                bh[nt][0] = vh.x; bh[nt][1] = vh.y;
                bl[nt][0] = vl.x; bl[nt][1] = vl.y;
            }
#pragma unroll
            for (int mt = 0; mt < 4; mt++) {
                const int tm = wm * 4 + mt;
                uint4 avh = *(const uint4*)(Ahb + ((ks * 8 + tm) * 32 + lane) * 4);
                uint4 avl = *(const uint4*)(Alb + ((ks * 8 + tm) * 32 + lane) * 4);
#pragma unroll
                for (int nt = 0; nt < 4; nt++) {
                    asm volatile(
                        "mma.sync.aligned.m16n8k16.row.col.f32.bf16.bf16.f32 "
                        "{%0,%1,%2,%3}, {%4,%5,%6,%7}, {%8,%9}, {%0,%1,%2,%3};"
                        : "+f"(acc[mt][nt][0]), "+f"(acc[mt][nt][1]),
                          "+f"(acc[mt][nt][2]), "+f"(acc[mt][nt][3])
                        : "r"(avh.x), "r"(avh.y), "r"(avh.z), "r"(avh.w),
                          "r"(bh[nt][0]), "r"(bh[nt][1]));
                    asm volatile(
                        "mma.sync.aligned.m16n8k16.row.col.f32.bf16.bf16.f32 "
                        "{%0,%1,%2,%3}, {%4,%5,%6,%7}, {%8,%9}, {%0,%1,%2,%3};"
                        : "+f"(acc[mt][nt][0]), "+f"(acc[mt][nt][1]),
                          "+f"(acc[mt][nt][2]), "+f"(acc[mt][nt][3])
                        : "r"(avh.x), "r"(avh.y), "r"(avh.z), "r"(avh.w),
                          "r"(bl[nt][0]), "r"(bl[nt][1]));
                    asm volatile(
                        "mma.sync.aligned.m16n8k16.row.col.f32.bf16.bf16.f32 "
                        "{%0,%1,%2,%3}, {%4,%5,%6,%7}, {%8,%9}, {%0,%1,%2,%3};"
                        : "+f"(acc[mt][nt][0]), "+f"(acc[mt][nt][1]),
                          "+f"(acc[mt][nt][2]), "+f"(acc[mt][nt][3])
                        : "r"(avl.x), "r"(avl.y), "r"(avl.z), "r"(avl.w),
                          "r"(bh[nt][0]), "r"(bh[nt][1]));
                }
            }
        }
        if (has_next) {
            store_tiles(smem_u + ((kb + 1) & 1) * 8192);
            __syncthreads();
        }
    }

#pragma unroll
    for (int mt = 0; mt < 4; mt++) {
        const int row0 = bm + wm * 64 + mt * 16 + (lane >> 2);
#pragma unroll
        for (int nt = 0; nt < 4; nt++) {
            const int col = bn + wn * 32 + nt * 8 + (lane & 3) * 2;
            *(float2*)(C + (size_t)row0 * N + col) = make_float2(acc[mt][nt][0], acc[mt][nt][1]);
            *(float2*)(C + (size_t)(row0 + 8) * N + col) = make_float2(acc[mt][nt][2], acc[mt][nt][3]);
        }
    }
}

// ---------------- dt = softplus(hs @ Win^T + dt_bias) ----------------
__global__ void dt_kernel(const float* __restrict__ hs, const float* __restrict__ Win,
                          const float* __restrict__ dtb) {
    __shared__ float srow[HIDDEN];
    __shared__ float red[256];
    const int l = blockIdx.x;
    for (int k = threadIdx.x; k < HIDDEN; k += 256) srow[k] = hs[(size_t)l * HIDDEN + k];
    __syncthreads();
    const int h = threadIdx.x & 31;
    const int part = threadIdx.x >> 5;
    const float* w = Win + (size_t)h * HIDDEN + part * 512;
    const float* s = srow + part * 512;
    float acc = 0.f;
#pragma unroll 4
    for (int k = 0; k < 512; k++) acc += s[k] * w[k];
    red[threadIdx.x] = acc;
    __syncthreads();
    if (threadIdx.x < 32) {
        float t = 0.f;
#pragma unroll
        for (int p = 0; p < 8; p++) t += red[p * 32 + h];
        t += dtb[h];
        float sp = fmaxf(t, 0.f) + log1pf(expf(-fabsf(t)));
        g_dt[l * NH + h] = sp;
    }
}

// ---------------- per-(chunk,head) inclusive cumsum of g = dt*A ----------------
__global__ void scan_kernel(const float* __restrict__ A_log) {
    const int hc = blockIdx.x;
    const int h = hc & (NH - 1);
    const int c = hc >> 5;
    const float A = -expf(A_log[h]);
    const int lane = threadIdx.x;
    float carry = 0.f;
    for (int s0 = 0; s0 < CHUNKS; s0 += 32) {
        const int l = c * CHUNKS + s0 + lane;
        float val = g_dt[l * NH + h] * A;
#pragma unroll
        for (int off = 1; off < 32; off <<= 1) {
            float n = __shfl_up_sync(0xffffffffu, val, off);
            if (lane >= off) val += n;
        }
        val += carry;
        g_G[l * NH + h] = val;
        carry = __shfl_sync(0xffffffffu, val, 31);
    }
    if (lane == 31) g_cdec[c * NH + h] = expf(carry);
}

// ---------------- RoPE in place ----------------
__global__ void rope_kernel(float* __restrict__ x, int nheads) {
    const long idx = (long)blockIdx.x * blockDim.x + threadIdx.x;
    const long total = (long)LSEQ * nheads * 64;
    if (idx >= total) return;
    const int d = (int)(idx & 63);
    const int h = (int)((idx >> 6) % nheads);
    const long l = idx / ((long)64 * nheads);
    const float inv = powf(10000.0f, -(2.0f * d) / 128.0f);
    const float ang = (float)l * inv;
    float cs, sn;
    __sincosf(ang, &sn, &cs);
    float* base = x + l * (size_t)(nheads * HD) + (size_t)h * HD;
    const float x1 = base[d];
    const float x2 = base[d + 64];
    base[d]      = x1 * cs - x2 * sn;
    base[d + 64] = x2 * cs + x1 * sn;
}

// ---------------- intra-chunk via tf32x3 tensor MMA ----------------
// grid (NC, NH), 256 threads (8 warps 2x4, warp tile 64x32).
// smem (u32 units): phase1 q A-frags @0/8192, k B-frags @16384/24576;
// phase2+3: P A-frags @0 (hi) / 16384 (lo); X B-frags @32768/40960;
// phase4: Kdec A-frags @0/8192, X @32768/40960.  Peak 49152 u32 = 192KB.
__global__ void __launch_bounds__(256, 1) intra_mma() {
    uint32_t* sm = (uint32_t*)dyn_smem;
    __shared__ float sG[128], sDt[128];
    const int c = blockIdx.x, h = blockIdx.y;
    const int kvh = h >> 2;
    const int tid = threadIdx.x;
    const int warp = tid >> 5, lane = tid & 31;
    const int wm = warp >> 2, wn = warp & 3;
    const float* qp = g_q + (size_t)(c * CHUNKS) * QDIM + (size_t)h * HD;
    const float* kp = g_k + (size_t)(c * CHUNKS) * KVDIM + (size_t)kvh * HD;
    const float* vp = g_v + (size_t)(c * CHUNKS) * KVDIM + (size_t)kvh * HD;

    if (tid < 128) {
        sG[tid] = g_G[(c * CHUNKS + tid) * NH + h];
        sDt[tid] = g_dt[(c * CHUNKS + tid) * NH + h];
    }
    __syncthreads();
    const float Glast = sG[127];

    float acc[4][4][4];
#pragma unroll
    for (int a = 0; a < 4; a++)
#pragma unroll
        for (int b = 0; b < 4; b++)
#pragma unroll
            for (int r = 0; r < 4; r++) acc[a][b][r] = 0.f;

    // ---- phase 1: S = q @ k^T (k-dim = head dim, two halves of 64) ----
    {
        uint32_t* qh = sm;
        uint32_t* ql = sm + 8192;
        uint32_t* kh = sm + 16384;
        uint32_t* kl = sm + 24576;
        for (int half = 0; half < 2; half++) {
            const int d0 = half * 64;
            __syncthreads();
#pragma unroll
            for (int i = 0; i < 8; i++) {
                const int idx = tid + i * 256;
                const int row = idx >> 4;
                const int dl = (idx & 15) * 4;
                float4 v = *(const float4*)(qp + (size_t)row * QDIM + d0 + dl);
                tf_store(qh, ql, aidx(row, dl + 0), v.x);
                tf_store(qh, ql, aidx(row, dl + 1), v.y);
                tf_store(qh, ql, aidx(row, dl + 2), v.z);
                tf_store(qh, ql, aidx(row, dl + 3), v.w);
                float4 w = *(const float4*)(kp + (size_t)row * KVDIM + d0 + dl);
                tf_store(kh, kl, bidx(row, dl + 0), w.x);
                tf_store(kh, kl, bidx(row, dl + 1), w.y);
                tf_store(kh, kl, bidx(row, dl + 2), w.z);
                tf_store(kh, kl, bidx(row, dl + 3), w.w);
            }
            __syncthreads();
#pragma unroll
            for (int ks = 0; ks < 8; ks++) {
                uint2 bhf[4], blf[4];
#pragma unroll
                for (int nt = 0; nt < 4; nt++) {
                    const int tn = wn * 4 + nt;
                    bhf[nt] = *(const uint2*)(kh + ((ks * 16 + tn) * 32 + lane) * 2);
                    blf[nt] = *(const uint2*)(kl + ((ks * 16 + tn) * 32 + lane) * 2);
                }
#pragma unroll
                for (int mt = 0; mt < 4; mt++) {
                    const int tm = wm * 4 + mt;
                    uint4 ah_ = *(const uint4*)(qh + ((ks * 8 + tm) * 32 + lane) * 4);
                    uint4 al_ = *(const uint4*)(ql + ((ks * 8 + tm) * 32 + lane) * 4);
                    const uint32_t ahr[4] = {ah_.x, ah_.y, ah_.z, ah_.w};
                    const uint32_t alr[4] = {al_.x, al_.y, al_.z, al_.w};
#pragma unroll
                    for (int nt = 0; nt < 4; nt++) {
                        mma_tf32(acc[mt][nt], ahr, bhf[nt].x, bhf[nt].y);
                        mma_tf32(acc[mt][nt], ahr, blf[nt].x, blf[nt].y);
                        mma_tf32(acc[mt][nt], alr, bhf[nt].x, bhf[nt].y);
                    }
                }
            }
        }
    }

    // ---- phase 2: causal decay mask -> P A-fragments in smem ----
    __syncthreads();
    {
        uint32_t* ph = sm;
        uint32_t* pl = sm + 16384;
#pragma unroll
        for (int mt = 0; mt < 4; mt++)
#pragma unroll
            for (int nt = 0; nt < 4; nt++)
#pragma unroll
                for (int r = 0; r < 4; r++) {
                    const int row = wm * 64 + mt * 16 + (lane >> 2) + ((r >> 1) << 3);
                    const int col = wn * 32 + nt * 8 + ((lane & 3) << 1) + (r & 1);
                    float p = 0.f;
                    if (row >= col) p = acc[mt][nt][r] * __expf(sG[row] - sG[col]);
                    const int idx = aidx(row, col);
                    uint32_t hv = f2tf(p);
                    ph[idx] = hv;
                    pl[idx] = f2tf(p - __uint_as_float(hv));
                }
    }
    __syncthreads();

    // ---- phase 3: y_intra = P @ X, X[j][e] = v[j][e]*dt[j] ----
#pragma unroll
    for (int a = 0; a < 4; a++)
#pragma unroll
        for (int b = 0; b < 4; b++)
#pragma unroll
            for (int r = 0; r < 4; r++) acc[a][b][r] = 0.f;
    {
        uint32_t* ph = sm;
        uint32_t* pl = sm + 16384;
        uint32_t* xh = sm + 32768;
        uint32_t* xl = sm + 40960;
        for (int half = 0; half < 2; half++) {
            const int j0 = half * 64;
            if (half) __syncthreads();
#pragma unroll
            for (int i = 0; i < 8; i++) {
                const int idx = tid + i * 256;
                const int jl = idx >> 5;
                const int e0 = (idx & 31) * 4;
                const float dtv = sDt[j0 + jl];
                float4 v = *(const float4*)(vp + (size_t)(j0 + jl) * KVDIM + e0);
                tf_store(xh, xl, bidx(e0 + 0, jl), v.x * dtv);
                tf_store(xh, xl, bidx(e0 + 1, jl), v.y * dtv);
                tf_store(xh, xl, bidx(e0 + 2, jl), v.z * dtv);
                tf_store(xh, xl, bidx(e0 + 3, jl), v.w * dtv);
            }
            __syncthreads();
#pragma unroll
            for (int ks = 0; ks < 8; ks++) {
                const int ksg = half * 8 + ks;
                uint2 bhf[4], blf[4];
#pragma unroll
                for (int nt = 0; nt < 4; nt++) {
                    const int tn = wn * 4 + nt;
                    bhf[nt] = *(const uint2*)(xh + ((ks * 16 + tn) * 32 + lane) * 2);
                    blf[nt] = *(const uint2*)(xl + ((ks * 16 + tn) * 32 + lane) * 2);
                }
#pragma unroll
                for (int mt = 0; mt < 4; mt++) {
                    const int tm = wm * 4 + mt;
                    uint4 ah_ = *(const uint4*)(ph + ((ksg * 8 + tm) * 32 + lane) * 4);
                    uint4 al_ = *(const uint4*)(pl + ((ksg * 8 + tm) * 32 + lane) * 4);
                    const uint32_t ahr[4] = {ah_.x, ah_.y, ah_.z, ah_.w};
                    const uint32_t alr[4] = {al_.x, al_.y, al_.z, al_.w};
#pragma unroll
                    for (int nt = 0; nt < 4; nt++) {
                        mma_tf32(acc[mt][nt], ahr, bhf[nt].x, bhf[nt].y);
                        mma_tf32(acc[mt][nt], ahr, blf[nt].x, blf[nt].y);
                        mma_tf32(acc[mt][nt], alr, bhf[nt].x, bhf[nt].y);
                    }
                }
            }
        }
    }
    // epilogue: y_intra -> g_y
#pragma unroll
    for (int mt = 0; mt < 4; mt++) {
        const int row0 = wm * 64 + mt * 16 + (lane >> 2);
#pragma unroll
        for (int nt = 0; nt < 4; nt++) {
            const int col = wn * 32 + nt * 8 + (lane & 3) * 2;
            float* y0 = g_y + (size_t)(c * CHUNKS + row0) * QDIM + (size_t)h * HD + col;
            float* y1 = g_y + (size_t)(c * CHUNKS + row0 + 8) * QDIM + (size_t)h * HD + col;
            *(float2*)y0 = make_float2(acc[mt][nt][0], acc[mt][nt][1]);
            *(float2*)y1 = make_float2(acc[mt][nt][2], acc[mt][nt][3]);
        }
    }

    // ---- phase 4: cstates[d][e] = sum_j k[j][d]*exp(Glast-G_j) * X[j][e] ----
#pragma unroll
    for (int a = 0; a < 4; a++)
#pragma unroll
        for (int b = 0; b < 4; b++)
#pragma unroll
            for (int r = 0; r < 4; r++) acc[a][b][r] = 0.f;
    {
        uint32_t* ah4 = sm;
        uint32_t* al4 = sm + 8192;
        uint32_t* xh = sm + 32768;
        uint32_t* xl = sm + 40960;
        for (int half = 0; half < 2; half++) {
            const int j0 = half * 64;
            __syncthreads();
#pragma unroll
            for (int i = 0; i < 8; i++) {
                const int idx = tid + i * 256;
                const int jl = idx >> 5;
                const int d4 = (idx & 31) * 4;
                const float w = __expf(Glast - sG[j0 + jl]);
                const float dtv = sDt[j0 + jl];
                float4 kv = *(const float4*)(kp + (size_t)(j0 + jl) * KVDIM + d4);
                tf_store(ah4, al4, aidx(d4 + 0, jl), kv.x * w);
                tf_store(ah4, al4, aidx(d4 + 1, jl), kv.y * w);
                tf_store(ah4, al4, aidx(d4 + 2, jl), kv.z * w);
                tf_store(ah4, al4, aidx(d4 + 3, jl), kv.w * w);
                float4 v = *(const float4*)(vp + (size_t)(j0 + jl) * KVDIM + d4);
                tf_store(xh, xl, bidx(d4 + 0, jl), v.x * dtv);
                tf_store(xh, xl, bidx(d4 + 1, jl), v.y * dtv);
                tf_store(xh, xl, bidx(d4 + 2, jl), v.z * dtv);
                tf_store(xh, xl, bidx(d4 + 3, jl), v.w * dtv);
            }
            __syncthreads();
#pragma unroll
            for (int ks = 0; ks < 8; ks++) {
                uint2 bhf[4], blf[4];
#pragma unroll
                for (int nt = 0; nt < 4; nt++) {
                    const int tn = wn * 4 + nt;
                    bhf[nt] = *(const uint2*)(xh + ((ks * 16 + tn) * 32 + lane) * 2);
                    blf[nt] = *(const uint2*)(xl + ((ks * 16 + tn) * 32 + lane) * 2);
                }
#pragma unroll
                for (int mt = 0; mt < 4; mt++) {
                    const int tm = wm * 4 + mt;
                    uint4 ah_ = *(const uint4*)(ah4 + ((ks * 8 + tm) * 32 + lane) * 4);
                    uint4 al_ = *(const uint4*)(al4 + ((ks * 8 + tm) * 32 + lane) * 4);
                    const uint32_t ahr[4] = {ah_.x, ah_.y, ah_.z, ah_.w};
                    const uint32_t alr[4] = {al_.x, al_.y, al_.z, al_.w};
#pragma unroll
                    for (int nt = 0; nt < 4; nt++) {
                        mma_tf32(acc[mt][nt], ahr, bhf[nt].x, bhf[nt].y);
                        mma_tf32(acc[mt][nt], ahr, blf[nt].x, blf[nt].y);
                        mma_tf32(acc[mt][nt], alr, bhf[nt].x, bhf[nt].y);
                    }
                }
            }
        }
    }
    float* csp = g_cs + (size_t)(c * NH + h) * HD * HD;
#pragma unroll
    for (int mt = 0; mt < 4; mt++) {
        const int row0 = wm * 64 + mt * 16 + (lane >> 2);
#pragma unroll
        for (int nt = 0; nt < 4; nt++) {
            const int col = wn * 32 + nt * 8 + (lane & 3) * 2;
            *(float2*)(csp + (size_t)row0 * HD + col) = make_float2(acc[mt][nt][0], acc[mt][nt][1]);
            *(float2*)(csp + (size_t)(row0 + 8) * HD + col) = make_float2(acc[mt][nt][2], acc[mt][nt][3]);
        }
    }
}

// ---------------- sequential chunk recurrence ----------------
__global__ void recur_kernel() {
    const int idx = blockIdx.x * blockDim.x + threadIdx.x;
    if (idx >= NH * HD * HD) return;
    const int h = idx / (HD * HD);
    const int de = idx % (HD * HD);
    float state = 0.f;
#pragma unroll 1
    for (int c = 0; c < NC; c++) {
        const size_t off = (size_t)(c * NH + h) * HD * HD + de;
        g_prev[off] = state;
        state = state * g_cdec[c * NH + h] + g_cs[off];
    }
}

// ---------------- inter-chunk via tf32x3 MMA + combine + RMSNorm + SiLU gate ----------------
// smem: A-frags @0/8192, B-frags @16384/24576 (128KB); then sY fp32 reuse.
__global__ void __launch_bounds__(256, 1) inter_mma(const float* __restrict__ gnorm) {
    uint32_t* sm = (uint32_t*)dyn_smem;
    __shared__ float sG[128], sScale[128], sGn[128];
    const int c = blockIdx.x, h = blockIdx.y;
    const int tid = threadIdx.x;
    const int warp = tid >> 5, lane = tid & 31;
    const int wm = warp >> 2, wn = warp & 3;
    const float* qp = g_q + (size_t)(c * CHUNKS) * QDIM + (size_t)h * HD;
    const float* pp = g_prev + (size_t)(c * NH + h) * HD * HD;

    if (tid < 128) {
        sG[tid] = g_G[(c * CHUNKS + tid) * NH + h];
        sGn[tid] = gnorm[tid];
    }
    __syncthreads();

    float acc[4][4][4];
#pragma unroll
    for (int a = 0; a < 4; a++)
#pragma unroll
        for (int b = 0; b < 4; b++)
#pragma unroll
            for (int r = 0; r < 4; r++) acc[a][b][r] = 0.f;

    {
        uint32_t* ah = sm;
        uint32_t* al = sm + 8192;
        uint32_t* bh = sm + 16384;
        uint32_t* bl = sm + 24576;
        for (int half = 0; half < 2; half++) {
            const int d0 = half * 64;
            __syncthreads();
#pragma unroll
            for (int i = 0; i < 8; i++) {
                const int idx = tid + i * 256;
                {   // A = q * exp(G): 128 rows x 16 quads
                    const int row = idx >> 4;
                    const int dl = (idx & 15) * 4;
                    const float eg = __expf(sG[row]);
                    float4 v = *(const float4*)(qp + (size_t)row * QDIM + d0 + dl);
                    tf_store(ah, al, aidx(row, dl + 0), v.x * eg);
                    tf_store(ah, al, aidx(row, dl + 1), v.y * eg);
                    tf_store(ah, al, aidx(row, dl + 2), v.z * eg);
                    tf_store(ah, al, aidx(row, dl + 3), v.w * eg);
                }
                {   // B = prev^T: 64 d-rows x 32 e-quads
                    const int dl = idx >> 5;
                    const int e0 = (idx & 31) * 4;
                    float4 v = *(const float4*)(pp + (size_t)(d0 + dl) * HD + e0);
                    tf_store(bh, bl, bidx(e0 + 0, dl), v.x);
                    tf_store(bh, bl, bidx(e0 + 1, dl), v.y);
                    tf_store(bh, bl, bidx(e0 + 2, dl), v.z);
                    tf_store(bh, bl, bidx(e0 + 3, dl), v.w);
                }
            }
            __syncthreads();
#pragma unroll
            for (int ks = 0; ks < 8; ks++) {
                uint2 bhf[4], blf[4];
#pragma unroll
                for (int nt = 0; nt < 4; nt++) {
                    const int tn = wn * 4 + nt;
                    bhf[nt] = *(const uint2*)(bh + ((ks * 16 + tn) * 32 + lane) * 2);
                    blf[nt] = *(const uint2*)(bl + ((ks * 16 + tn) * 32 + lane) * 2);
                }
#pragma unroll
                for (int mt = 0; mt < 4; mt++) {
                    const int tm = wm * 4 + mt;
                    uint4 ah_ = *(const uint4*)(ah + ((ks * 8 + tm) * 32 + lane) * 4);
                    uint4 al_ = *(const uint4*)(al + ((ks * 8 + tm) * 32 + lane) * 4);
                    const uint32_t ahr[4] = {ah_.x, ah_.y, ah_.z, ah_.w};
                    const uint32_t alr[4] = {al_.x, al_.y, al_.z, al_.w};
#pragma unroll
                    for (int nt = 0; nt < 4; nt++) {
                        mma_tf32(acc[mt][nt], ahr, bhf[nt].x, bhf[nt].y);
                        mma_tf32(acc[mt][nt], ahr, blf[nt].x, blf[nt].y);
                        mma_tf32(acc[mt][nt], alr, bhf[nt].x, bhf[nt].y);
                    }
                }
            }
        }
    }
    __syncthreads();

    // combine with y_intra into sY
    float* sY = (float*)dyn_smem;   // 128*129 fp32
#pragma unroll
    for (int mt = 0; mt < 4; mt++) {
        const int row0 = wm * 64 + mt * 16 + (lane >> 2);
#pragma unroll
        for (int nt = 0; nt < 4; nt++) {
            const int col = wn * 32 + nt * 8 + (lane & 3) * 2;
            const float* y0 = g_y + (size_t)(c * CHUNKS + row0) * QDIM + (size_t)h * HD + col;
            const float* y1 = g_y + (size_t)(c * CHUNKS + row0 + 8) * QDIM + (size_t)h * HD + col;
            sY[row0 * 129 + col]     = acc[mt][nt][0] + y0[0];
            sY[row0 * 129 + col + 1] = acc[mt][nt][1] + y0[1];
            sY[(row0 + 8) * 129 + col]     = acc[mt][nt][2] + y1[0];
            sY[(row0 + 8) * 129 + col + 1] = acc[mt][nt][3] + y1[1];
        }
    }
    __syncthreads();

    if (tid < 128) {
        float s = 0.f;
#pragma unroll 4
        for (int e = 0; e < 128; e++) {
            float t = sY[tid * 129 + e];
            s += t * t;
        }
        sScale[tid] = rsqrtf(s * (1.0f / 128.0f) + 1e-5f);
    }
    __syncthreads();

    for (int idx = tid; idx < 128 * 128; idx += 256) {
        const int i = idx >> 7, e = idx & 127;
        const size_t off = (size_t)(c * CHUNKS + i) * QDIM + (size_t)h * HD + e;
        const float gv = g_gate[off];
        const float sig = 1.f / (1.f + expf(-gv));
        g_y[off] = sY[i * 129 + e] * sScale[i] * sGn[e] * gv * sig;
    }
}

// ---------------- launch ----------------
extern "C" void kernel_launch(void* const* d_in, const int* in_sizes, int n_in,
                              void* d_out, int out_size) {
    const float* hs      = (const float*)d_in[0];
    const float* Wq      = (const float*)d_in[1];
    const float* Wk      = (const float*)d_in[2];
    const float* Wv      = (const float*)d_in[3];
    const float* Wo      = (const float*)d_in[4];
    const float* Wg      = (const float*)d_in[5];
    const float* Win     = (const float*)d_in[6];
    const float* dt_bias = (const float*)d_in[7];
    const float* A_log   = (const float*)d_in[8];
    const float* gnorm   = (const float*)d_in[9];
    float* out = (float*)d_out;

    float *q, *k, *v, *gate, *y;
    cudaGetSymbolAddress((void**)&q, g_q);
    cudaGetSymbolAddress((void**)&k, g_k);
    cudaGetSymbolAddress((void**)&v, g_v);
    cudaGetSymbolAddress((void**)&gate, g_gate);
    cudaGetSymbolAddress((void**)&y, g_y);

    const int SMEM_GEMM  = 16384 * (int)sizeof(unsigned);  // 64KB
    const int SMEM_INTRA = 49152 * (int)sizeof(unsigned);  // 192KB
    const int SMEM_INTER = 32768 * (int)sizeof(unsigned);  // 128KB
    cudaFuncSetAttribute(gemm_bf16x3, cudaFuncAttributeMaxDynamicSharedMemorySize, SMEM_GEMM);
    cudaFuncSetAttribute(intra_mma, cudaFuncAttributeMaxDynamicSharedMemorySize, SMEM_INTRA);
    cudaFuncSetAttribute(inter_mma, cudaFuncAttributeMaxDynamicSharedMemorySize, SMEM_INTER);

    // projections (tensor core, bf16x3 compensated, fp32 inputs)
    gemm_bf16x3<<<dim3(QDIM / 128, LSEQ / 128), 256, SMEM_GEMM>>>(hs, Wq, q, LSEQ, QDIM, HIDDEN);
    gemm_bf16x3<<<dim3(KVDIM / 128, LSEQ / 128), 256, SMEM_GEMM>>>(hs, Wk, k, LSEQ, KVDIM, HIDDEN);
    gemm_bf16x3<<<dim3(KVDIM / 128, LSEQ / 128), 256, SMEM_GEMM>>>(hs, Wv, v, LSEQ, KVDIM, HIDDEN);
    gemm_bf16x3<<<dim3(QDIM / 128, LSEQ / 128), 256, SMEM_GEMM>>>(hs, Wg, gate, LSEQ, QDIM, HIDDEN);
    dt_kernel<<<LSEQ, 256>>>(hs, Win, dt_bias);
    scan_kernel<<<NC * NH, 32>>>(A_log);

    // rope
    {
        long tq = (long)LSEQ * NH * 64;
        rope_kernel<<<(unsigned)((tq + 255) / 256), 256>>>(q, NH);
        long tk = (long)LSEQ * NKV * 64;
        rope_kernel<<<(unsigned)((tk + 255) / 256), 256>>>(k, NKV);
    }

    // attention (tensor-core tf32x3)
    intra_mma<<<dim3(NC, NH), 256, SMEM_INTRA>>>();
    recur_kernel<<<(NH * HD * HD + 1023) / 1024, 1024>>>();
    inter_mma<<<dim3(NC, NH), 256, SMEM_INTER>>>(gnorm);

    // output projection
    gemm_bf16x3<<<dim3(HIDDEN / 128, LSEQ / 128), 256, SMEM_GEMM>>>(y, Wo, out, LSEQ, HIDDEN, QDIM);
}

// round 9
// speedup vs baseline: 1.0764x; 1.0764x over previous
#include <cuda_runtime.h>
#include <cuda_bf16.h>
#include <math.h>
#include <stdint.h>

#define LSEQ   4096
#define HIDDEN 4096
#define NH     32
#define NKV    8
#define HD     128
#define CHUNKS 128
#define NC     32
#define QDIM   4096   // NH*HD
#define KVDIM  1024   // NKV*HD

// single dynamic smem declaration for ALL kernels
extern __shared__ __align__(1024) unsigned char dyn_smem[];

// ---------------- scratch (static device globals; no allocation) ----------------
__device__ float g_q[(size_t)LSEQ * QDIM];
__device__ float g_k[(size_t)LSEQ * KVDIM];
__device__ float g_v[(size_t)LSEQ * KVDIM];
__device__ float g_gate[(size_t)LSEQ * QDIM];
__device__ float g_y[(size_t)LSEQ * QDIM];
__device__ float g_dt[LSEQ * NH];
__device__ float g_G[LSEQ * NH];
__device__ float g_cdec[NC * NH];
__device__ float g_cs[(size_t)NC * NH * HD * HD];
__device__ float g_prev[(size_t)NC * NH * HD * HD];

__device__ __forceinline__ unsigned pack_bf2(float a, float b) {
    __nv_bfloat162 t = __floats2bfloat162_rn(a, b);
    return reinterpret_cast<unsigned&>(t);
}

// ---------------- bf16x3 tensor-core GEMM, 128x256 CTA / 64x64 warp tile ----------------
// C[M,N] = A[M,K] @ B[N,K]^T, fp32 acc, MMAs hh+hl+lh (m16n8k16 bf16).
// 256 threads (8 warps 2x4). smem per buffer (u32): Ah@0[2048], Al@2048, Bh@4096[4096],
// Bl@8192[4096]; 2 buffers x 48KB = 96KB. M%128==0, N%256==0, K%32==0.
__global__ void __launch_bounds__(256, 1) gemm_big(const float* __restrict__ A,
                                                   const float* __restrict__ B,
                                                   float* __restrict__ C,
                                                   int M, int N, int K) {
    unsigned* smem_u = (unsigned*)dyn_smem;
    const int tid = threadIdx.x;
    const int warp = tid >> 5, lane = tid & 31;
    const int wm = warp >> 2, wn = warp & 3;   // 2 x 4 warps, warp tile 64x64
    const int bm = blockIdx.y * 128, bn = blockIdx.x * 256;

    float acc[4][8][4];
#pragma unroll
    for (int a = 0; a < 4; a++)
#pragma unroll
        for (int b = 0; b < 8; b++)
#pragma unroll
            for (int c = 0; c < 4; c++) acc[a][b][c] = 0.f;

    // staging: c4/ks/ki fixed per thread; rows advance by 32 per iteration
    const int c4 = tid & 7;
    const int k0 = c4 * 4;
    const int ks0 = c4 >> 2;
    const int ki = (c4 & 3) * 4;
    const int row0 = tid >> 3;            // 0..31

    const float* a_base = A + (size_t)(bm + row0) * K + k0;   // +i*32*K
    const float* b_base = B + (size_t)(bn + row0) * K + k0;
    const size_t gstride = (size_t)32 * K;

    // A fragment store base (i advances tm by 2 -> +256)
    const int riA = row0 & 15, tmA = row0 >> 4;
    const int laneA = (riA & 7) * 4 + ((ki & 7) >> 1);
    const int regA = (riA >> 3) + ((ki >> 3) << 1);
    const int a_st0 = ((ks0 * 8 + tmA) * 32 + laneA) * 4 + regA;
    // B fragment store base (i advances tn by 4 -> +256)
    const int tnB = row0 >> 3, ciB = row0 & 7;
    const int laneB = ciB * 4 + ((ki & 7) >> 1);
    const int regB = ki >> 3;
    const int b_st0 = ((ks0 * 32 + tnB) * 32 + laneB) * 2 + regB;

    float4 ar[4], br[8];
#pragma unroll
    for (int i = 0; i < 4; i++) ar[i] = *(const float4*)(a_base + i * gstride);
#pragma unroll
    for (int i = 0; i < 8; i++) br[i] = *(const float4*)(b_base + i * gstride);

    auto store_tiles = [&](unsigned* base) {
        unsigned* Ah = base;
        unsigned* Al = base + 2048;
        unsigned* Bh = base + 4096;
        unsigned* Bl = base + 8192;
#pragma unroll
        for (int i = 0; i < 4; i++) {
            float4 v = ar[i];
            __nv_bfloat162 h01 = __floats2bfloat162_rn(v.x, v.y);
            __nv_bfloat162 h23 = __floats2bfloat162_rn(v.z, v.w);
            float2 f01 = __bfloat1622float2(h01);
            float2 f23 = __bfloat1622float2(h23);
            const int st = a_st0 + i * 256;
            Ah[st]     = reinterpret_cast<unsigned&>(h01);
            Ah[st + 4] = reinterpret_cast<unsigned&>(h23);
            Al[st]     = pack_bf2(v.x - f01.x, v.y - f01.y);
            Al[st + 4] = pack_bf2(v.z - f23.x, v.w - f23.y);
        }
#pragma unroll
        for (int i = 0; i < 8; i++) {
            float4 v = br[i];
            __nv_bfloat162 h01 = __floats2bfloat162_rn(v.x, v.y);
            __nv_bfloat162 h23 = __floats2bfloat162_rn(v.z, v.w);
            float2 f01 = __bfloat1622float2(h01);
            float2 f23 = __bfloat1622float2(h23);
            const int st = b_st0 + i * 256;
            Bh[st]     = reinterpret_cast<unsigned&>(h01);
            Bh[st + 2] = reinterpret_cast<unsigned&>(h23);
            Bl[st]     = pack_bf2(v.x - f01.x, v.y - f01.y);
            Bl[st + 2] = pack_bf2(v.z - f23.x, v.w - f23.y);
        }
    };

    store_tiles(smem_u);
    __syncthreads();

    const int nk = K >> 5;
    for (int kb = 0; kb < nk; kb++) {
        const int cur = kb & 1;
        const bool has_next = (kb + 1) < nk;
        if (has_next) {
            const int off = (kb + 1) * 32;
#pragma unroll
            for (int i = 0; i < 4; i++) ar[i] = *(const float4*)(a_base + i * gstride + off);
#pragma unroll
            for (int i = 0; i < 8; i++) br[i] = *(const float4*)(b_base + i * gstride + off);
        }
        const unsigned* base = smem_u + cur * 12288;
        const unsigned* Ahb = base;
        const unsigned* Alb = base + 2048;
        const unsigned* Bhb = base + 4096;
        const unsigned* Blb = base + 8192;
#pragma unroll
        for (int ks = 0; ks < 2; ks++) {
            unsigned bh[8][2], bl[8][2];
#pragma unroll
            for (int nt = 0; nt < 8; nt++) {
                const int tn = wn * 8 + nt;
                uint2 vh = *(const uint2*)(Bhb + ((ks * 32 + tn) * 32 + lane) * 2);
                uint2 vl = *(const uint2*)(Blb + ((ks * 32 + tn) * 32 + lane) * 2);
                bh[nt][0] = vh.x; bh[nt][1] = vh.y;
                bl[nt][0] = vl.x; bl[nt][1] = vl.y;
            }
#pragma unroll
            for (int mt = 0; mt < 4; mt++) {
                const int tm = wm * 4 + mt;
                uint4 avh = *(const uint4*)(Ahb + ((ks * 8 + tm) * 32 + lane) * 4);
                uint4 avl = *(const uint4*)(Alb + ((ks * 8 + tm) * 32 + lane) * 4);
#pragma unroll
                for (int nt = 0; nt < 8; nt++) {
                    asm volatile(
                        "mma.sync.aligned.m16n8k16.row.col.f32.bf16.bf16.f32 "
                        "{%0,%1,%2,%3}, {%4,%5,%6,%7}, {%8,%9}, {%0,%1,%2,%3};"
                        : "+f"(acc[mt][nt][0]), "+f"(acc[mt][nt][1]),
                          "+f"(acc[mt][nt][2]), "+f"(acc[mt][nt][3])
                        : "r"(avh.x), "r"(avh.y), "r"(avh.z), "r"(avh.w),
                          "r"(bh[nt][0]), "r"(bh[nt][1]));
                    asm volatile(
                        "mma.sync.aligned.m16n8k16.row.col.f32.bf16.bf16.f32 "
                        "{%0,%1,%2,%3}, {%4,%5,%6,%7}, {%8,%9}, {%0,%1,%2,%3};"
                        : "+f"(acc[mt][nt][0]), "+f"(acc[mt][nt][1]),
                          "+f"(acc[mt][nt][2]), "+f"(acc[mt][nt][3])
                        : "r"(avh.x), "r"(avh.y), "r"(avh.z), "r"(avh.w),
                          "r"(bl[nt][0]), "r"(bl[nt][1]));
                    asm volatile(
                        "mma.sync.aligned.m16n8k16.row.col.f32.bf16.bf16.f32 "
                        "{%0,%1,%2,%3}, {%4,%5,%6,%7}, {%8,%9}, {%0,%1,%2,%3};"
                        : "+f"(acc[mt][nt][0]), "+f"(acc[mt][nt][1]),
                          "+f"(acc[mt][nt][2]), "+f"(acc[mt][nt][3])
                        : "r"(avl.x), "r"(avl.y), "r"(avl.z), "r"(avl.w),
                          "r"(bh[nt][0]), "r"(bh[nt][1]));
                }
            }
        }
        if (has_next) {
            store_tiles(smem_u + ((kb + 1) & 1) * 12288);
            __syncthreads();
        }
    }

    // epilogue
#pragma unroll
    for (int mt = 0; mt < 4; mt++) {
        const int row0e = bm + wm * 64 + mt * 16 + (lane >> 2);
#pragma unroll
        for (int nt = 0; nt < 8; nt++) {
            const int col = bn + wn * 64 + nt * 8 + (lane & 3) * 2;
            *(float2*)(C + (size_t)row0e * N + col) = make_float2(acc[mt][nt][0], acc[mt][nt][1]);
            *(float2*)(C + (size_t)(row0e + 8) * N + col) = make_float2(acc[mt][nt][2], acc[mt][nt][3]);
        }
    }
}

// ---------------- dt = softplus(hs @ Win^T + dt_bias) ----------------
__global__ void dt_kernel(const float* __restrict__ hs, const float* __restrict__ Win,
                          const float* __restrict__ dtb) {
    __shared__ float srow[HIDDEN];
    __shared__ float red[256];
    const int l = blockIdx.x;
    for (int k = threadIdx.x; k < HIDDEN; k += 256) srow[k] = hs[(size_t)l * HIDDEN + k];
    __syncthreads();
    const int h = threadIdx.x & 31;
    const int part = threadIdx.x >> 5;
    const float* w = Win + (size_t)h * HIDDEN + part * 512;
    const float* s = srow + part * 512;
    float acc = 0.f;
#pragma unroll 4
    for (int k = 0; k < 512; k++) acc += s[k] * w[k];
    red[threadIdx.x] = acc;
    __syncthreads();
    if (threadIdx.x < 32) {
        float t = 0.f;
#pragma unroll
        for (int p = 0; p < 8; p++) t += red[p * 32 + h];
        t += dtb[h];
        float sp = fmaxf(t, 0.f) + log1pf(expf(-fabsf(t)));
        g_dt[l * NH + h] = sp;
    }
}

// ---------------- per-(chunk,head) inclusive cumsum of g = dt*A ----------------
__global__ void scan_kernel(const float* __restrict__ A_log) {
    const int hc = blockIdx.x;
    const int h = hc & (NH - 1);
    const int c = hc >> 5;
    const float A = -expf(A_log[h]);
    const int lane = threadIdx.x;
    float carry = 0.f;
    for (int s0 = 0; s0 < CHUNKS; s0 += 32) {
        const int l = c * CHUNKS + s0 + lane;
        float val = g_dt[l * NH + h] * A;
#pragma unroll
        for (int off = 1; off < 32; off <<= 1) {
            float n = __shfl_up_sync(0xffffffffu, val, off);
            if (lane >= off) val += n;
        }
        val += carry;
        g_G[l * NH + h] = val;
        carry = __shfl_sync(0xffffffffu, val, 31);
    }
    if (lane == 31) g_cdec[c * NH + h] = expf(carry);
}

// ---------------- RoPE in place ----------------
__global__ void rope_kernel(float* __restrict__ x, int nheads) {
    const long idx = (long)blockIdx.x * blockDim.x + threadIdx.x;
    const long total = (long)LSEQ * nheads * 64;
    if (idx >= total) return;
    const int d = (int)(idx & 63);
    const int h = (int)((idx >> 6) % nheads);
    const long l = idx / ((long)64 * nheads);
    const float inv = powf(10000.0f, -(2.0f * d) / 128.0f);
    const float ang = (float)l * inv;
    float cs, sn;
    __sincosf(ang, &sn, &cs);
    float* base = x + l * (size_t)(nheads * HD) + (size_t)h * HD;
    const float x1 = base[d];
    const float x2 = base[d + 64];
    base[d]      = x1 * cs - x2 * sn;
    base[d + 64] = x2 * cs + x1 * sn;
}

// ---------------- intra-chunk: scores, decay mask, y_intra, cstates (round-3 FFMA) ----------------
__global__ void intra_kernel() {
    float* smem = (float*)dyn_smem;
    float* sP = smem;                 // 128*129, P^T (stored [j][i])
    float* sA = sP + 128 * 129;       // 16*128
    float* sB = sA + 16 * 128;        // 16*128
    __shared__ float sG[128];
    __shared__ float sDt[128];

    const int c = blockIdx.x, h = blockIdx.y;
    const int kvh = h >> 2;
    const int tid = threadIdx.x;
    const int tr = tid >> 4, tc = tid & 15;
    const float* qp = g_q + (size_t)(c * CHUNKS) * QDIM + (size_t)h * HD;
    const float* kp = g_k + (size_t)(c * CHUNKS) * KVDIM + (size_t)kvh * HD;
    const float* vp = g_v + (size_t)(c * CHUNKS) * KVDIM + (size_t)kvh * HD;

    if (tid < 128) {
        sG[tid] = g_G[(c * CHUNKS + tid) * NH + h];
        sDt[tid] = g_dt[(c * CHUNKS + tid) * NH + h];
    }
    __syncthreads();
    const float Glast = sG[127];

    float acc[8][8];
#pragma unroll
    for (int i = 0; i < 8; i++)
#pragma unroll
        for (int j = 0; j < 8; j++) acc[i][j] = 0.f;

    const int rowA = tid >> 1;
    const int kk0 = (tid & 1) * 8;
    for (int d0 = 0; d0 < HD; d0 += 16) {
        const float* ap = qp + (size_t)rowA * QDIM + d0 + kk0;
        float4 a0 = *(const float4*)ap;
        float4 a1 = *(const float4*)(ap + 4);
        sA[(kk0 + 0) * 128 + rowA] = a0.x;
        sA[(kk0 + 1) * 128 + rowA] = a0.y;
        sA[(kk0 + 2) * 128 + rowA] = a0.z;
        sA[(kk0 + 3) * 128 + rowA] = a0.w;
        sA[(kk0 + 4) * 128 + rowA] = a1.x;
        sA[(kk0 + 5) * 128 + rowA] = a1.y;
        sA[(kk0 + 6) * 128 + rowA] = a1.z;
        sA[(kk0 + 7) * 128 + rowA] = a1.w;
        const float* bp = kp + (size_t)rowA * KVDIM + d0 + kk0;
        float4 b0 = *(const float4*)bp;
        float4 b1 = *(const float4*)(bp + 4);
        sB[(kk0 + 0) * 128 + rowA] = b0.x;
        sB[(kk0 + 1) * 128 + rowA] = b0.y;
        sB[(kk0 + 2) * 128 + rowA] = b0.z;
        sB[(kk0 + 3) * 128 + rowA] = b0.w;
        sB[(kk0 + 4) * 128 + rowA] = b1.x;
        sB[(kk0 + 5) * 128 + rowA] = b1.y;
        sB[(kk0 + 6) * 128 + rowA] = b1.z;
        sB[(kk0 + 7) * 128 + rowA] = b1.w;
        __syncthreads();
#pragma unroll
        for (int kk = 0; kk < 16; kk++) {
            float av[8], bv[8];
#pragma unroll
            for (int i = 0; i < 8; i++) av[i] = sA[kk * 128 + tr * 8 + i];
#pragma unroll
            for (int j = 0; j < 8; j++) bv[j] = sB[kk * 128 + tc * 8 + j];
#pragma unroll
            for (int i = 0; i < 8; i++)
#pragma unroll
                for (int j = 0; j < 8; j++) acc[i][j] += av[i] * bv[j];
        }
        __syncthreads();
    }

#pragma unroll
    for (int ii = 0; ii < 8; ii++) {
        const int i = tr * 8 + ii;
        const float Gi = sG[i];
#pragma unroll
        for (int jj = 0; jj < 8; jj++) {
            const int j = tc * 8 + jj;
            const float p = (i >= j) ? acc[ii][jj] * expf(Gi - sG[j]) : 0.f;
            sP[j * 129 + i] = p;
        }
    }
    __syncthreads();

#pragma unroll
    for (int i = 0; i < 8; i++)
#pragma unroll
        for (int j = 0; j < 8; j++) acc[i][j] = 0.f;
    {
        const int kkl = tid >> 4;
        const int e0 = (tid & 15) * 8;
        for (int j0 = 0; j0 < 128; j0 += 16) {
            const float dtv = sDt[j0 + kkl];
            const float* xp = vp + (size_t)(j0 + kkl) * KVDIM + e0;
            float4 x0 = *(const float4*)xp;
            float4 x1 = *(const float4*)(xp + 4);
            sB[kkl * 128 + e0 + 0] = x0.x * dtv;
            sB[kkl * 128 + e0 + 1] = x0.y * dtv;
            sB[kkl * 128 + e0 + 2] = x0.z * dtv;
            sB[kkl * 128 + e0 + 3] = x0.w * dtv;
            sB[kkl * 128 + e0 + 4] = x1.x * dtv;
            sB[kkl * 128 + e0 + 5] = x1.y * dtv;
            sB[kkl * 128 + e0 + 6] = x1.z * dtv;
            sB[kkl * 128 + e0 + 7] = x1.w * dtv;
            __syncthreads();
#pragma unroll
            for (int kk = 0; kk < 16; kk++) {
                float av[8], bv[8];
#pragma unroll
                for (int i = 0; i < 8; i++) av[i] = sP[(j0 + kk) * 129 + tr * 8 + i];
#pragma unroll
                for (int j = 0; j < 8; j++) bv[j] = sB[kk * 128 + tc * 8 + j];
#pragma unroll
                for (int i = 0; i < 8; i++)
#pragma unroll
                    for (int j = 0; j < 8; j++) acc[i][j] += av[i] * bv[j];
            }
            __syncthreads();
        }
    }
#pragma unroll
    for (int ii = 0; ii < 8; ii++) {
        float* yp = g_y + (size_t)(c * CHUNKS + tr * 8 + ii) * QDIM + (size_t)h * HD + tc * 8;
        *(float4*)yp = make_float4(acc[ii][0], acc[ii][1], acc[ii][2], acc[ii][3]);
        *(float4*)(yp + 4) = make_float4(acc[ii][4], acc[ii][5], acc[ii][6], acc[ii][7]);
    }

#pragma unroll
    for (int i = 0; i < 8; i++)
#pragma unroll
        for (int j = 0; j < 8; j++) acc[i][j] = 0.f;
    {
        const int kkl = tid >> 4;
        const int e0 = (tid & 15) * 8;
        for (int j0 = 0; j0 < 128; j0 += 16) {
            const float w = expf(Glast - sG[j0 + kkl]);
            const float dtv = sDt[j0 + kkl];
            const float* kp2 = kp + (size_t)(j0 + kkl) * KVDIM + e0;
            const float* xp = vp + (size_t)(j0 + kkl) * KVDIM + e0;
            float4 k0v = *(const float4*)kp2;
            float4 k1v = *(const float4*)(kp2 + 4);
            float4 x0 = *(const float4*)xp;
            float4 x1 = *(const float4*)(xp + 4);
            sA[kkl * 128 + e0 + 0] = k0v.x * w;
            sA[kkl * 128 + e0 + 1] = k0v.y * w;
            sA[kkl * 128 + e0 + 2] = k0v.z * w;
            sA[kkl * 128 + e0 + 3] = k0v.w * w;
            sA[kkl * 128 + e0 + 4] = k1v.x * w;
            sA[kkl * 128 + e0 + 5] = k1v.y * w;
            sA[kkl * 128 + e0 + 6] = k1v.z * w;
            sA[kkl * 128 + e0 + 7] = k1v.w * w;
            sB[kkl * 128 + e0 + 0] = x0.x * dtv;
            sB[kkl * 128 + e0 + 1] = x0.y * dtv;
            sB[kkl * 128 + e0 + 2] = x0.z * dtv;
            sB[kkl * 128 + e0 + 3] = x0.w * dtv;
            sB[kkl * 128 + e0 + 4] = x1.x * dtv;
            sB[kkl * 128 + e0 + 5] = x1.y * dtv;
            sB[kkl * 128 + e0 + 6] = x1.z * dtv;
            sB[kkl * 128 + e0 + 7] = x1.w * dtv;
            __syncthreads();
#pragma unroll
            for (int kk = 0; kk < 16; kk++) {
                float av[8], bv[8];
#pragma unroll
                for (int i = 0; i < 8; i++) av[i] = sA[kk * 128 + tr * 8 + i];
#pragma unroll
                for (int j = 0; j < 8; j++) bv[j] = sB[kk * 128 + tc * 8 + j];
#pragma unroll
                for (int i = 0; i < 8; i++)
#pragma unroll
                    for (int j = 0; j < 8; j++) acc[i][j] += av[i] * bv[j];
            }
            __syncthreads();
        }
    }
    float* csp = g_cs + (size_t)(c * NH + h) * HD * HD;
#pragma unroll
    for (int ii = 0; ii < 8; ii++) {
        float* cp = csp + (size_t)(tr * 8 + ii) * HD + tc * 8;
        *(float4*)cp = make_float4(acc[ii][0], acc[ii][1], acc[ii][2], acc[ii][3]);
        *(float4*)(cp + 4) = make_float4(acc[ii][4], acc[ii][5], acc[ii][6], acc[ii][7]);
    }
}

// ---------------- sequential chunk recurrence ----------------
__global__ void recur_kernel() {
    const int idx = blockIdx.x * blockDim.x + threadIdx.x;
    if (idx >= NH * HD * HD) return;
    const int h = idx / (HD * HD);
    const int de = idx % (HD * HD);
    float state = 0.f;
#pragma unroll 1
    for (int c = 0; c < NC; c++) {
        const size_t off = (size_t)(c * NH + h) * HD * HD + de;
        g_prev[off] = state;
        state = state * g_cdec[c * NH + h] + g_cs[off];
    }
}

// ---------------- inter-chunk + combine + RMSNorm + SiLU gate (round-3 FFMA) ----------------
__global__ void inter_kernel(const float* __restrict__ gnorm) {
    float* smem = (float*)dyn_smem;
    float* sY = smem;               // 128*129
    float* sA = sY + 128 * 129;     // 16*128
    float* sB = sA + 16 * 128;      // 16*128
    __shared__ float sG[128];
    __shared__ float sScale[128];
    __shared__ float sGn[128];

    const int c = blockIdx.x, h = blockIdx.y;
    const int tid = threadIdx.x;
    const int tr = tid >> 4, tc = tid & 15;
    const float* qp = g_q + (size_t)(c * CHUNKS) * QDIM + (size_t)h * HD;
    const float* pp = g_prev + (size_t)(c * NH + h) * HD * HD;

    if (tid < 128) {
        sG[tid] = g_G[(c * CHUNKS + tid) * NH + h];
        sGn[tid] = gnorm[tid];
    }
    __syncthreads();

    float acc[8][8];
#pragma unroll
    for (int i = 0; i < 8; i++)
#pragma unroll
        for (int j = 0; j < 8; j++) acc[i][j] = 0.f;

    const int rowA = tid >> 1;
    const int kk0 = (tid & 1) * 8;
    const int kkl = tid >> 4;
    const int e0 = (tid & 15) * 8;
    for (int d0 = 0; d0 < HD; d0 += 16) {
        const float eg = expf(sG[rowA]);
        const float* ap = qp + (size_t)rowA * QDIM + d0 + kk0;
        float4 a0 = *(const float4*)ap;
        float4 a1 = *(const float4*)(ap + 4);
        sA[(kk0 + 0) * 128 + rowA] = a0.x * eg;
        sA[(kk0 + 1) * 128 + rowA] = a0.y * eg;
        sA[(kk0 + 2) * 128 + rowA] = a0.z * eg;
        sA[(kk0 + 3) * 128 + rowA] = a0.w * eg;
        sA[(kk0 + 4) * 128 + rowA] = a1.x * eg;
        sA[(kk0 + 5) * 128 + rowA] = a1.y * eg;
        sA[(kk0 + 6) * 128 + rowA] = a1.z * eg;
        sA[(kk0 + 7) * 128 + rowA] = a1.w * eg;
        const float* bp = pp + (size_t)(d0 + kkl) * HD + e0;
        float4 b0 = *(const float4*)bp;
        float4 b1 = *(const float4*)(bp + 4);
        sB[kkl * 128 + e0 + 0] = b0.x;
        sB[kkl * 128 + e0 + 1] = b0.y;
        sB[kkl * 128 + e0 + 2] = b0.z;
        sB[kkl * 128 + e0 + 3] = b0.w;
        sB[kkl * 128 + e0 + 4] = b1.x;
        sB[kkl * 128 + e0 + 5] = b1.y;
        sB[kkl * 128 + e0 + 6] = b1.z;
        sB[kkl * 128 + e0 + 7] = b1.w;
        __syncthreads();
#pragma unroll
        for (int kk = 0; kk < 16; kk++) {
            float av[8], bv[8];
#pragma unroll
            for (int i = 0; i < 8; i++) av[i] = sA[kk * 128 + tr * 8 + i];
#pragma unroll
            for (int j = 0; j < 8; j++) bv[j] = sB[kk * 128 + tc * 8 + j];
#pragma unroll
            for (int i = 0; i < 8; i++)
#pragma unroll
                for (int j = 0; j < 8; j++) acc[i][j] += av[i] * bv[j];
        }
        __syncthreads();
    }

#pragma unroll
    for (int ii = 0; ii < 8; ii++) {
        const int i = tr * 8 + ii;
        const float* yin = g_y + (size_t)(c * CHUNKS + i) * QDIM + (size_t)h * HD + tc * 8;
#pragma unroll
        for (int jj = 0; jj < 8; jj++) {
            sY[i * 129 + tc * 8 + jj] = acc[ii][jj] + yin[jj];
        }
    }
    __syncthreads();

    if (tid < 128) {
        float s = 0.f;
#pragma unroll 4
        for (int e = 0; e < 128; e++) {
            float t = sY[tid * 129 + e];
            s += t * t;
        }
        sScale[tid] = rsqrtf(s * (1.0f / 128.0f) + 1e-5f);
    }
    __syncthreads();

    for (int idx = tid; idx < 128 * 128; idx += 256) {
        const int i = idx >> 7, e = idx & 127;
        const size_t off = (size_t)(c * CHUNKS + i) * QDIM + (size_t)h * HD + e;
        const float gv = g_gate[off];
        const float sig = 1.f / (1.f + expf(-gv));
        g_y[off] = sY[i * 129 + e] * sScale[i] * sGn[e] * gv * sig;
    }
}

// ---------------- launch ----------------
extern "C" void kernel_launch(void* const* d_in, const int* in_sizes, int n_in,
                              void* d_out, int out_size) {
    const float* hs      = (const float*)d_in[0];
    const float* Wq      = (const float*)d_in[1];
    const float* Wk      = (const float*)d_in[2];
    const float* Wv      = (const float*)d_in[3];
    const float* Wo      = (const float*)d_in[4];
    const float* Wg      = (const float*)d_in[5];
    const float* Win     = (const float*)d_in[6];
    const float* dt_bias = (const float*)d_in[7];
    const float* A_log   = (const float*)d_in[8];
    const float* gnorm   = (const float*)d_in[9];
    float* out = (float*)d_out;

    float *q, *k, *v, *gate, *y;
    cudaGetSymbolAddress((void**)&q, g_q);
    cudaGetSymbolAddress((void**)&k, g_k);
    cudaGetSymbolAddress((void**)&v, g_v);
    cudaGetSymbolAddress((void**)&gate, g_gate);
    cudaGetSymbolAddress((void**)&y, g_y);

    const int SMEM_BIG = (128 * 129 + 2 * 16 * 128) * (int)sizeof(float);
    cudaFuncSetAttribute(intra_kernel, cudaFuncAttributeMaxDynamicSharedMemorySize, SMEM_BIG);
    cudaFuncSetAttribute(inter_kernel, cudaFuncAttributeMaxDynamicSharedMemorySize, SMEM_BIG);
    const int SMEM_GEMM = 2 * 12288 * (int)sizeof(unsigned);  // 96KB
    cudaFuncSetAttribute(gemm_big, cudaFuncAttributeMaxDynamicSharedMemorySize, SMEM_GEMM);

    // projections (tensor core, bf16x3 compensated; 128x256 CTA, 64x64 warp tile)
    gemm_big<<<dim3(QDIM / 256, LSEQ / 128), 256, SMEM_GEMM>>>(hs, Wq, q, LSEQ, QDIM, HIDDEN);
    gemm_big<<<dim3(KVDIM / 256, LSEQ / 128), 256, SMEM_GEMM>>>(hs, Wk, k, LSEQ, KVDIM, HIDDEN);
    gemm_big<<<dim3(KVDIM / 256, LSEQ / 128), 256, SMEM_GEMM>>>(hs, Wv, v, LSEQ, KVDIM, HIDDEN);
    gemm_big<<<dim3(QDIM / 256, LSEQ / 128), 256, SMEM_GEMM>>>(hs, Wg, gate, LSEQ, QDIM, HIDDEN);
    dt_kernel<<<LSEQ, 256>>>(hs, Win, dt_bias);
    scan_kernel<<<NC * NH, 32>>>(A_log);

    // rope
    {
        long tq = (long)LSEQ * NH * 64;
        rope_kernel<<<(unsigned)((tq + 255) / 256), 256>>>(q, NH);
        long tk = (long)LSEQ * NKV * 64;
        rope_kernel<<<(unsigned)((tk + 255) / 256), 256>>>(k, NKV);
    }

    // attention (round-3 FFMA versions)
    intra_kernel<<<dim3(NC, NH), 256, SMEM_BIG>>>();
    recur_kernel<<<(NH * HD * HD + 1023) / 1024, 1024>>>();
    inter_kernel<<<dim3(NC, NH), 256, SMEM_BIG>>>(gnorm);

    // output projection
    gemm_big<<<dim3(HIDDEN / 256, LSEQ / 128), 256, SMEM_GEMM>>>(y, Wo, out, LSEQ, HIDDEN, QDIM);
}

// round 10
// speedup vs baseline: 1.1220x; 1.0424x over previous
#include <cuda_runtime.h>
#include <cuda_bf16.h>
#include <math.h>
#include <stdint.h>

#define LSEQ   4096
#define HIDDEN 4096
#define NH     32
#define NKV    8
#define HD     128
#define CHUNKS 128
#define NC     32
#define QDIM   4096   // NH*HD
#define KVDIM  1024   // NKV*HD

// single dynamic smem declaration for ALL kernels
extern __shared__ __align__(1024) unsigned char dyn_smem[];

// ---------------- scratch (static device globals; no allocation) ----------------
__device__ float g_q[(size_t)LSEQ * QDIM];
__device__ float g_k[(size_t)LSEQ * KVDIM];
__device__ float g_v[(size_t)LSEQ * KVDIM];
__device__ float g_gate[(size_t)LSEQ * QDIM];
__device__ float g_y[(size_t)LSEQ * QDIM];
__device__ float g_dt[LSEQ * NH];
__device__ float g_G[LSEQ * NH];
__device__ float g_cdec[NC * NH];
__device__ float g_cs[(size_t)NC * NH * HD * HD];
__device__ float g_prev[(size_t)NC * NH * HD * HD];

__device__ __forceinline__ unsigned pack_bf2(float a, float b) {
    __nv_bfloat162 t = __floats2bfloat162_rn(a, b);
    return reinterpret_cast<unsigned&>(t);
}

// ---------------- bf16x3 tensor-core GEMM, 128x256 CTA / 512 threads / 64x32 warp tile ----
// C[M,N] = A[M,K] @ B[N,K]^T, fp32 acc, MMAs hh+hl+lh (m16n8k16 bf16).
// 16 warps (2 x 8 grid). smem per buffer (u32): Ah@0[2048], Al@2048, Bh@4096[4096],
// Bl@8192[4096]; 2 buffers x 48KB = 96KB. M%128==0, N%256==0, K%32==0.
__global__ void __launch_bounds__(512, 1) gemm_big(const float* __restrict__ A,
                                                   const float* __restrict__ B,
                                                   float* __restrict__ C,
                                                   int M, int N, int K) {
    unsigned* smem_u = (unsigned*)dyn_smem;
    const int tid = threadIdx.x;
    const int warp = tid >> 5, lane = tid & 31;
    const int wm = warp >> 3, wn = warp & 7;   // 2 x 8 warps, warp tile 64x32
    const int bm = blockIdx.y * 128, bn = blockIdx.x * 256;

    float acc[4][4][4];
#pragma unroll
    for (int a = 0; a < 4; a++)
#pragma unroll
        for (int b = 0; b < 4; b++)
#pragma unroll
            for (int c = 0; c < 4; c++) acc[a][b][c] = 0.f;

    // staging: c4 fixed per thread; rows advance by 64 per chunk index
    const int c4 = tid & 7;
    const int k0 = c4 * 4;
    const int ks0 = c4 >> 2;
    const int ki = (c4 & 3) * 4;
    const int row0 = tid >> 3;            // 0..63

    const float* a_base = A + (size_t)(bm + row0) * K + k0;   // +i*64*K (i<2)
    const float* b_base = B + (size_t)(bn + row0) * K + k0;   // +i*64*K (i<4)
    const size_t gstride = (size_t)64 * K;

    // A fragment store base; row += 64 -> tm += 4 -> st += 512
    const int riA = row0 & 15, tmA = row0 >> 4;
    const int laneA = (riA & 7) * 4 + ((ki & 7) >> 1);
    const int regA = (riA >> 3) + ((ki >> 3) << 1);
    const int a_st0 = ((ks0 * 8 + tmA) * 32 + laneA) * 4 + regA;
    // B fragment store base; row += 64 -> tn += 8 -> st += 512
    const int tnB = row0 >> 3, ciB = row0 & 7;
    const int laneB = ciB * 4 + ((ki & 7) >> 1);
    const int regB = ki >> 3;
    const int b_st0 = ((ks0 * 32 + tnB) * 32 + laneB) * 2 + regB;

    float4 ar[2], br[4];
#pragma unroll
    for (int i = 0; i < 2; i++) ar[i] = *(const float4*)(a_base + i * gstride);
#pragma unroll
    for (int i = 0; i < 4; i++) br[i] = *(const float4*)(b_base + i * gstride);

    auto store_tiles = [&](unsigned* base) {
        unsigned* Ah = base;
        unsigned* Al = base + 2048;
        unsigned* Bh = base + 4096;
        unsigned* Bl = base + 8192;
#pragma unroll
        for (int i = 0; i < 2; i++) {
            float4 v = ar[i];
            __nv_bfloat162 h01 = __floats2bfloat162_rn(v.x, v.y);
            __nv_bfloat162 h23 = __floats2bfloat162_rn(v.z, v.w);
            float2 f01 = __bfloat1622float2(h01);
            float2 f23 = __bfloat1622float2(h23);
            const int st = a_st0 + i * 512;
            Ah[st]     = reinterpret_cast<unsigned&>(h01);
            Ah[st + 4] = reinterpret_cast<unsigned&>(h23);
            Al[st]     = pack_bf2(v.x - f01.x, v.y - f01.y);
            Al[st + 4] = pack_bf2(v.z - f23.x, v.w - f23.y);
        }
#pragma unroll
        for (int i = 0; i < 4; i++) {
            float4 v = br[i];
            __nv_bfloat162 h01 = __floats2bfloat162_rn(v.x, v.y);
            __nv_bfloat162 h23 = __floats2bfloat162_rn(v.z, v.w);
            float2 f01 = __bfloat1622float2(h01);
            float2 f23 = __bfloat1622float2(h23);
            const int st = b_st0 + i * 512;
            Bh[st]     = reinterpret_cast<unsigned&>(h01);
            Bh[st + 2] = reinterpret_cast<unsigned&>(h23);
            Bl[st]     = pack_bf2(v.x - f01.x, v.y - f01.y);
            Bl[st + 2] = pack_bf2(v.z - f23.x, v.w - f23.y);
        }
    };

    store_tiles(smem_u);
    __syncthreads();

    const int nk = K >> 5;
    for (int kb = 0; kb < nk; kb++) {
        const int cur = kb & 1;
        const bool has_next = (kb + 1) < nk;
        if (has_next) {
            const int off = (kb + 1) * 32;
#pragma unroll
            for (int i = 0; i < 2; i++) ar[i] = *(const float4*)(a_base + i * gstride + off);
#pragma unroll
            for (int i = 0; i < 4; i++) br[i] = *(const float4*)(b_base + i * gstride + off);
        }
        const unsigned* base = smem_u + cur * 12288;
        const unsigned* Ahb = base;
        const unsigned* Alb = base + 2048;
        const unsigned* Bhb = base + 4096;
        const unsigned* Blb = base + 8192;
#pragma unroll
        for (int ks = 0; ks < 2; ks++) {
            unsigned bh[4][2], bl[4][2];
#pragma unroll
            for (int nt = 0; nt < 4; nt++) {
                const int tn = wn * 4 + nt;
                uint2 vh = *(const uint2*)(Bhb + ((ks * 32 + tn) * 32 + lane) * 2);
                uint2 vl = *(const uint2*)(Blb + ((ks * 32 + tn) * 32 + lane) * 2);
                bh[nt][0] = vh.x; bh[nt][1] = vh.y;
                bl[nt][0] = vl.x; bl[nt][1] = vl.y;
            }
#pragma unroll
            for (int mt = 0; mt < 4; mt++) {
                const int tm = wm * 4 + mt;
                uint4 avh = *(const uint4*)(Ahb + ((ks * 8 + tm) * 32 + lane) * 4);
                uint4 avl = *(const uint4*)(Alb + ((ks * 8 + tm) * 32 + lane) * 4);
#pragma unroll
                for (int nt = 0; nt < 4; nt++) {
                    asm volatile(
                        "mma.sync.aligned.m16n8k16.row.col.f32.bf16.bf16.f32 "
                        "{%0,%1,%2,%3}, {%4,%5,%6,%7}, {%8,%9}, {%0,%1,%2,%3};"
                        : "+f"(acc[mt][nt][0]), "+f"(acc[mt][nt][1]),
                          "+f"(acc[mt][nt][2]), "+f"(acc[mt][nt][3])
                        : "r"(avh.x), "r"(avh.y), "r"(avh.z), "r"(avh.w),
                          "r"(bh[nt][0]), "r"(bh[nt][1]));
                    asm volatile(
                        "mma.sync.aligned.m16n8k16.row.col.f32.bf16.bf16.f32 "
                        "{%0,%1,%2,%3}, {%4,%5,%6,%7}, {%8,%9}, {%0,%1,%2,%3};"
                        : "+f"(acc[mt][nt][0]), "+f"(acc[mt][nt][1]),
                          "+f"(acc[mt][nt][2]), "+f"(acc[mt][nt][3])
                        : "r"(avh.x), "r"(avh.y), "r"(avh.z), "r"(avh.w),
                          "r"(bl[nt][0]), "r"(bl[nt][1]));
                    asm volatile(
                        "mma.sync.aligned.m16n8k16.row.col.f32.bf16.bf16.f32 "
                        "{%0,%1,%2,%3}, {%4,%5,%6,%7}, {%8,%9}, {%0,%1,%2,%3};"
                        : "+f"(acc[mt][nt][0]), "+f"(acc[mt][nt][1]),
                          "+f"(acc[mt][nt][2]), "+f"(acc[mt][nt][3])
                        : "r"(avl.x), "r"(avl.y), "r"(avl.z), "r"(avl.w),
                          "r"(bh[nt][0]), "r"(bh[nt][1]));
                }
            }
        }
        if (has_next) {
            store_tiles(smem_u + ((kb + 1) & 1) * 12288);
            __syncthreads();
        }
    }

    // epilogue
#pragma unroll
    for (int mt = 0; mt < 4; mt++) {
        const int row0e = bm + wm * 64 + mt * 16 + (lane >> 2);
#pragma unroll
        for (int nt = 0; nt < 4; nt++) {
            const int col = bn + wn * 32 + nt * 8 + (lane & 3) * 2;
            *(float2*)(C + (size_t)row0e * N + col) = make_float2(acc[mt][nt][0], acc[mt][nt][1]);
            *(float2*)(C + (size_t)(row0e + 8) * N + col) = make_float2(acc[mt][nt][2], acc[mt][nt][3]);
        }
    }
}

// ---------------- dt = softplus(hs @ Win^T + dt_bias) ----------------
__global__ void dt_kernel(const float* __restrict__ hs, const float* __restrict__ Win,
                          const float* __restrict__ dtb) {
    __shared__ float srow[HIDDEN];
    __shared__ float red[256];
    const int l = blockIdx.x;
    for (int k = threadIdx.x; k < HIDDEN; k += 256) srow[k] = hs[(size_t)l * HIDDEN + k];
    __syncthreads();
    const int h = threadIdx.x & 31;
    const int part = threadIdx.x >> 5;
    const float* w = Win + (size_t)h * HIDDEN + part * 512;
    const float* s = srow + part * 512;
    float acc = 0.f;
#pragma unroll 4
    for (int k = 0; k < 512; k++) acc += s[k] * w[k];
    red[threadIdx.x] = acc;
    __syncthreads();
    if (threadIdx.x < 32) {
        float t = 0.f;
#pragma unroll
        for (int p = 0; p < 8; p++) t += red[p * 32 + h];
        t += dtb[h];
        float sp = fmaxf(t, 0.f) + log1pf(expf(-fabsf(t)));
        g_dt[l * NH + h] = sp;
    }
}

// ---------------- per-(chunk,head) inclusive cumsum of g = dt*A ----------------
__global__ void scan_kernel(const float* __restrict__ A_log) {
    const int hc = blockIdx.x;
    const int h = hc & (NH - 1);
    const int c = hc >> 5;
    const float A = -expf(A_log[h]);
    const int lane = threadIdx.x;
    float carry = 0.f;
    for (int s0 = 0; s0 < CHUNKS; s0 += 32) {
        const int l = c * CHUNKS + s0 + lane;
        float val = g_dt[l * NH + h] * A;
#pragma unroll
        for (int off = 1; off < 32; off <<= 1) {
            float n = __shfl_up_sync(0xffffffffu, val, off);
            if (lane >= off) val += n;
        }
        val += carry;
        g_G[l * NH + h] = val;
        carry = __shfl_sync(0xffffffffu, val, 31);
    }
    if (lane == 31) g_cdec[c * NH + h] = expf(carry);
}

// ---------------- RoPE in place ----------------
__global__ void rope_kernel(float* __restrict__ x, int nheads) {
    const long idx = (long)blockIdx.x * blockDim.x + threadIdx.x;
    const long total = (long)LSEQ * nheads * 64;
    if (idx >= total) return;
    const int d = (int)(idx & 63);
    const int h = (int)((idx >> 6) % nheads);
    const long l = idx / ((long)64 * nheads);
    const float inv = powf(10000.0f, -(2.0f * d) / 128.0f);
    const float ang = (float)l * inv;
    float cs, sn;
    __sincosf(ang, &sn, &cs);
    float* base = x + l * (size_t)(nheads * HD) + (size_t)h * HD;
    const float x1 = base[d];
    const float x2 = base[d + 64];
    base[d]      = x1 * cs - x2 * sn;
    base[d + 64] = x2 * cs + x1 * sn;
}

// ---------------- intra-chunk: scores, decay mask, y_intra, cstates (round-3 FFMA) ----------------
__global__ void intra_kernel() {
    float* smem = (float*)dyn_smem;
    float* sP = smem;                 // 128*129, P^T (stored [j][i])
    float* sA = sP + 128 * 129;       // 16*128
    float* sB = sA + 16 * 128;        // 16*128
    __shared__ float sG[128];
    __shared__ float sDt[128];

    const int c = blockIdx.x, h = blockIdx.y;
    const int kvh = h >> 2;
    const int tid = threadIdx.x;
    const int tr = tid >> 4, tc = tid & 15;
    const float* qp = g_q + (size_t)(c * CHUNKS) * QDIM + (size_t)h * HD;
    const float* kp = g_k + (size_t)(c * CHUNKS) * KVDIM + (size_t)kvh * HD;
    const float* vp = g_v + (size_t)(c * CHUNKS) * KVDIM + (size_t)kvh * HD;

    if (tid < 128) {
        sG[tid] = g_G[(c * CHUNKS + tid) * NH + h];
        sDt[tid] = g_dt[(c * CHUNKS + tid) * NH + h];
    }
    __syncthreads();
    const float Glast = sG[127];

    float acc[8][8];
#pragma unroll
    for (int i = 0; i < 8; i++)
#pragma unroll
        for (int j = 0; j < 8; j++) acc[i][j] = 0.f;

    const int rowA = tid >> 1;
    const int kk0 = (tid & 1) * 8;
    for (int d0 = 0; d0 < HD; d0 += 16) {
        const float* ap = qp + (size_t)rowA * QDIM + d0 + kk0;
        float4 a0 = *(const float4*)ap;
        float4 a1 = *(const float4*)(ap + 4);
        sA[(kk0 + 0) * 128 + rowA] = a0.x;
        sA[(kk0 + 1) * 128 + rowA] = a0.y;
        sA[(kk0 + 2) * 128 + rowA] = a0.z;
        sA[(kk0 + 3) * 128 + rowA] = a0.w;
        sA[(kk0 + 4) * 128 + rowA] = a1.x;
        sA[(kk0 + 5) * 128 + rowA] = a1.y;
        sA[(kk0 + 6) * 128 + rowA] = a1.z;
        sA[(kk0 + 7) * 128 + rowA] = a1.w;
        const float* bp = kp + (size_t)rowA * KVDIM + d0 + kk0;
        float4 b0 = *(const float4*)bp;
        float4 b1 = *(const float4*)(bp + 4);
        sB[(kk0 + 0) * 128 + rowA] = b0.x;
        sB[(kk0 + 1) * 128 + rowA] = b0.y;
        sB[(kk0 + 2) * 128 + rowA] = b0.z;
        sB[(kk0 + 3) * 128 + rowA] = b0.w;
        sB[(kk0 + 4) * 128 + rowA] = b1.x;
        sB[(kk0 + 5) * 128 + rowA] = b1.y;
        sB[(kk0 + 6) * 128 + rowA] = b1.z;
        sB[(kk0 + 7) * 128 + rowA] = b1.w;
        __syncthreads();
#pragma unroll
        for (int kk = 0; kk < 16; kk++) {
            float av[8], bv[8];
#pragma unroll
            for (int i = 0; i < 8; i++) av[i] = sA[kk * 128 + tr * 8 + i];
#pragma unroll
            for (int j = 0; j < 8; j++) bv[j] = sB[kk * 128 + tc * 8 + j];
#pragma unroll
            for (int i = 0; i < 8; i++)
#pragma unroll
                for (int j = 0; j < 8; j++) acc[i][j] += av[i] * bv[j];
        }
        __syncthreads();
    }

#pragma unroll
    for (int ii = 0; ii < 8; ii++) {
        const int i = tr * 8 + ii;
        const float Gi = sG[i];
#pragma unroll
        for (int jj = 0; jj < 8; jj++) {
            const int j = tc * 8 + jj;
            const float p = (i >= j) ? acc[ii][jj] * expf(Gi - sG[j]) : 0.f;
            sP[j * 129 + i] = p;
        }
    }
    __syncthreads();

#pragma unroll
    for (int i = 0; i < 8; i++)
#pragma unroll
        for (int j = 0; j < 8; j++) acc[i][j] = 0.f;
    {
        const int kkl = tid >> 4;
        const int e0 = (tid & 15) * 8;
        for (int j0 = 0; j0 < 128; j0 += 16) {
            const float dtv = sDt[j0 + kkl];
            const float* xp = vp + (size_t)(j0 + kkl) * KVDIM + e0;
            float4 x0 = *(const float4*)xp;
            float4 x1 = *(const float4*)(xp + 4);
            sB[kkl * 128 + e0 + 0] = x0.x * dtv;
            sB[kkl * 128 + e0 + 1] = x0.y * dtv;
            sB[kkl * 128 + e0 + 2] = x0.z * dtv;
            sB[kkl * 128 + e0 + 3] = x0.w * dtv;
            sB[kkl * 128 + e0 + 4] = x1.x * dtv;
            sB[kkl * 128 + e0 + 5] = x1.y * dtv;
            sB[kkl * 128 + e0 + 6] = x1.z * dtv;
            sB[kkl * 128 + e0 + 7] = x1.w * dtv;
            __syncthreads();
#pragma unroll
            for (int kk = 0; kk < 16; kk++) {
                float av[8], bv[8];
#pragma unroll
                for (int i = 0; i < 8; i++) av[i] = sP[(j0 + kk) * 129 + tr * 8 + i];
#pragma unroll
                for (int j = 0; j < 8; j++) bv[j] = sB[kk * 128 + tc * 8 + j];
#pragma unroll
                for (int i = 0; i < 8; i++)
#pragma unroll
                    for (int j = 0; j < 8; j++) acc[i][j] += av[i] * bv[j];
            }
            __syncthreads();
        }
    }
#pragma unroll
    for (int ii = 0; ii < 8; ii++) {
        float* yp = g_y + (size_t)(c * CHUNKS + tr * 8 + ii) * QDIM + (size_t)h * HD + tc * 8;
        *(float4*)yp = make_float4(acc[ii][0], acc[ii][1], acc[ii][2], acc[ii][3]);
        *(float4*)(yp + 4) = make_float4(acc[ii][4], acc[ii][5], acc[ii][6], acc[ii][7]);
    }

#pragma unroll
    for (int i = 0; i < 8; i++)
#pragma unroll
        for (int j = 0; j < 8; j++) acc[i][j] = 0.f;
    {
        const int kkl = tid >> 4;
        const int e0 = (tid & 15) * 8;
        for (int j0 = 0; j0 < 128; j0 += 16) {
            const float w = expf(Glast - sG[j0 + kkl]);
            const float dtv = sDt[j0 + kkl];
            const float* kp2 = kp + (size_t)(j0 + kkl) * KVDIM + e0;
            const float* xp = vp + (size_t)(j0 + kkl) * KVDIM + e0;
            float4 k0v = *(const float4*)kp2;
            float4 k1v = *(const float4*)(kp2 + 4);
            float4 x0 = *(const float4*)xp;
            float4 x1 = *(const float4*)(xp + 4);
            sA[kkl * 128 + e0 + 0] = k0v.x * w;
            sA[kkl * 128 + e0 + 1] = k0v.y * w;
            sA[kkl * 128 + e0 + 2] = k0v.z * w;
            sA[kkl * 128 + e0 + 3] = k0v.w * w;
            sA[kkl * 128 + e0 + 4] = k1v.x * w;
            sA[kkl * 128 + e0 + 5] = k1v.y * w;
            sA[kkl * 128 + e0 + 6] = k1v.z * w;
            sA[kkl * 128 + e0 + 7] = k1v.w * w;
            sB[kkl * 128 + e0 + 0] = x0.x * dtv;
            sB[kkl * 128 + e0 + 1] = x0.y * dtv;
            sB[kkl * 128 + e0 + 2] = x0.z * dtv;
            sB[kkl * 128 + e0 + 3] = x0.w * dtv;
            sB[kkl * 128 + e0 + 4] = x1.x * dtv;
            sB[kkl * 128 + e0 + 5] = x1.y * dtv;
            sB[kkl * 128 + e0 + 6] = x1.z * dtv;
            sB[kkl * 128 + e0 + 7] = x1.w * dtv;
            __syncthreads();
#pragma unroll
            for (int kk = 0; kk < 16; kk++) {
                float av[8], bv[8];
#pragma unroll
                for (int i = 0; i < 8; i++) av[i] = sA[kk * 128 + tr * 8 + i];
#pragma unroll
                for (int j = 0; j < 8; j++) bv[j] = sB[kk * 128 + tc * 8 + j];
#pragma unroll
                for (int i = 0; i < 8; i++)
#pragma unroll
                    for (int j = 0; j < 8; j++) acc[i][j] += av[i] * bv[j];
            }
            __syncthreads();
        }
    }
    float* csp = g_cs + (size_t)(c * NH + h) * HD * HD;
#pragma unroll
    for (int ii = 0; ii < 8; ii++) {
        float* cp = csp + (size_t)(tr * 8 + ii) * HD + tc * 8;
        *(float4*)cp = make_float4(acc[ii][0], acc[ii][1], acc[ii][2], acc[ii][3]);
        *(float4*)(cp + 4) = make_float4(acc[ii][4], acc[ii][5], acc[ii][6], acc[ii][7]);
    }
}

// ---------------- sequential chunk recurrence ----------------
__global__ void recur_kernel() {
    const int idx = blockIdx.x * blockDim.x + threadIdx.x;
    if (idx >= NH * HD * HD) return;
    const int h = idx / (HD * HD);
    const int de = idx % (HD * HD);
    float state = 0.f;
#pragma unroll 1
    for (int c = 0; c < NC; c++) {
        const size_t off = (size_t)(c * NH + h) * HD * HD + de;
        g_prev[off] = state;
        state = state * g_cdec[c * NH + h] + g_cs[off];
    }
}

// ---------------- inter-chunk + combine + RMSNorm + SiLU gate (round-3 FFMA) ----------------
__global__ void inter_kernel(const float* __restrict__ gnorm) {
    float* smem = (float*)dyn_smem;
    float* sY = smem;               // 128*129
    float* sA = sY + 128 * 129;     // 16*128
    float* sB = sA + 16 * 128;      // 16*128
    __shared__ float sG[128];
    __shared__ float sScale[128];
    __shared__ float sGn[128];

    const int c = blockIdx.x, h = blockIdx.y;
    const int tid = threadIdx.x;
    const int tr = tid >> 4, tc = tid & 15;
    const float* qp = g_q + (size_t)(c * CHUNKS) * QDIM + (size_t)h * HD;
    const float* pp = g_prev + (size_t)(c * NH + h) * HD * HD;

    if (tid < 128) {
        sG[tid] = g_G[(c * CHUNKS + tid) * NH + h];
        sGn[tid] = gnorm[tid];
    }
    __syncthreads();

    float acc[8][8];
#pragma unroll
    for (int i = 0; i < 8; i++)
#pragma unroll
        for (int j = 0; j < 8; j++) acc[i][j] = 0.f;

    const int rowA = tid >> 1;
    const int kk0 = (tid & 1) * 8;
    const int kkl = tid >> 4;
    const int e0 = (tid & 15) * 8;
    for (int d0 = 0; d0 < HD; d0 += 16) {
        const float eg = expf(sG[rowA]);
        const float* ap = qp + (size_t)rowA * QDIM + d0 + kk0;
        float4 a0 = *(const float4*)ap;
        float4 a1 = *(const float4*)(ap + 4);
        sA[(kk0 + 0) * 128 + rowA] = a0.x * eg;
        sA[(kk0 + 1) * 128 + rowA] = a0.y * eg;
        sA[(kk0 + 2) * 128 + rowA] = a0.z * eg;
        sA[(kk0 + 3) * 128 + rowA] = a0.w * eg;
        sA[(kk0 + 4) * 128 + rowA] = a1.x * eg;
        sA[(kk0 + 5) * 128 + rowA] = a1.y * eg;
        sA[(kk0 + 6) * 128 + rowA] = a1.z * eg;
        sA[(kk0 + 7) * 128 + rowA] = a1.w * eg;
        const float* bp = pp + (size_t)(d0 + kkl) * HD + e0;
        float4 b0 = *(const float4*)bp;
        float4 b1 = *(const float4*)(bp + 4);
        sB[kkl * 128 + e0 + 0] = b0.x;
        sB[kkl * 128 + e0 + 1] = b0.y;
        sB[kkl * 128 + e0 + 2] = b0.z;
        sB[kkl * 128 + e0 + 3] = b0.w;
        sB[kkl * 128 + e0 + 4] = b1.x;
        sB[kkl * 128 + e0 + 5] = b1.y;
        sB[kkl * 128 + e0 + 6] = b1.z;
        sB[kkl * 128 + e0 + 7] = b1.w;
        __syncthreads();
#pragma unroll
        for (int kk = 0; kk < 16; kk++) {
            float av[8], bv[8];
#pragma unroll
            for (int i = 0; i < 8; i++) av[i] = sA[kk * 128 + tr * 8 + i];
#pragma unroll
            for (int j = 0; j < 8; j++) bv[j] = sB[kk * 128 + tc * 8 + j];
#pragma unroll
            for (int i = 0; i < 8; i++)
#pragma unroll
                for (int j = 0; j < 8; j++) acc[i][j] += av[i] * bv[j];
        }
        __syncthreads();
    }

#pragma unroll
    for (int ii = 0; ii < 8; ii++) {
        const int i = tr * 8 + ii;
        const float* yin = g_y + (size_t)(c * CHUNKS + i) * QDIM + (size_t)h * HD + tc * 8;
#pragma unroll
        for (int jj = 0; jj < 8; jj++) {
            sY[i * 129 + tc * 8 + jj] = acc[ii][jj] + yin[jj];
        }
    }
    __syncthreads();

    if (tid < 128) {
        float s = 0.f;
#pragma unroll 4
        for (int e = 0; e < 128; e++) {
            float t = sY[tid * 129 + e];
            s += t * t;
        }
        sScale[tid] = rsqrtf(s * (1.0f / 128.0f) + 1e-5f);
    }
    __syncthreads();

    for (int idx = tid; idx < 128 * 128; idx += 256) {
        const int i = idx >> 7, e = idx & 127;
        const size_t off = (size_t)(c * CHUNKS + i) * QDIM + (size_t)h * HD + e;
        const float gv = g_gate[off];
        const float sig = 1.f / (1.f + expf(-gv));
        g_y[off] = sY[i * 129 + e] * sScale[i] * sGn[e] * gv * sig;
    }
}

// ---------------- launch ----------------
extern "C" void kernel_launch(void* const* d_in, const int* in_sizes, int n_in,
                              void* d_out, int out_size) {
    const float* hs      = (const float*)d_in[0];
    const float* Wq      = (const float*)d_in[1];
    const float* Wk      = (const float*)d_in[2];
    const float* Wv      = (const float*)d_in[3];
    const float* Wo      = (const float*)d_in[4];
    const float* Wg      = (const float*)d_in[5];
    const float* Win     = (const float*)d_in[6];
    const float* dt_bias = (const float*)d_in[7];
    const float* A_log   = (const float*)d_in[8];
    const float* gnorm   = (const float*)d_in[9];
    float* out = (float*)d_out;

    float *q, *k, *v, *gate, *y;
    cudaGetSymbolAddress((void**)&q, g_q);
    cudaGetSymbolAddress((void**)&k, g_k);
    cudaGetSymbolAddress((void**)&v, g_v);
    cudaGetSymbolAddress((void**)&gate, g_gate);
    cudaGetSymbolAddress((void**)&y, g_y);

    const int SMEM_BIG = (128 * 129 + 2 * 16 * 128) * (int)sizeof(float);
    cudaFuncSetAttribute(intra_kernel, cudaFuncAttributeMaxDynamicSharedMemorySize, SMEM_BIG);
    cudaFuncSetAttribute(inter_kernel, cudaFuncAttributeMaxDynamicSharedMemorySize, SMEM_BIG);
    const int SMEM_GEMM = 2 * 12288 * (int)sizeof(unsigned);  // 96KB
    cudaFuncSetAttribute(gemm_big, cudaFuncAttributeMaxDynamicSharedMemorySize, SMEM_GEMM);

    // projections (tensor core, bf16x3; 128x256 CTA, 512 threads, 64x32 warp tile)
    gemm_big<<<dim3(QDIM / 256, LSEQ / 128), 512, SMEM_GEMM>>>(hs, Wq, q, LSEQ, QDIM, HIDDEN);
    gemm_big<<<dim3(KVDIM / 256, LSEQ / 128), 512, SMEM_GEMM>>>(hs, Wk, k, LSEQ, KVDIM, HIDDEN);
    gemm_big<<<dim3(KVDIM / 256, LSEQ / 128), 512, SMEM_GEMM>>>(hs, Wv, v, LSEQ, KVDIM, HIDDEN);
    gemm_big<<<dim3(QDIM / 256, LSEQ / 128), 512, SMEM_GEMM>>>(hs, Wg, gate, LSEQ, QDIM, HIDDEN);
    dt_kernel<<<LSEQ, 256>>>(hs, Win, dt_bias);
    scan_kernel<<<NC * NH, 32>>>(A_log);

    // rope
    {
        long tq = (long)LSEQ * NH * 64;
        rope_kernel<<<(unsigned)((tq + 255) / 256), 256>>>(q, NH);
        long tk = (long)LSEQ * NKV * 64;
        rope_kernel<<<(unsigned)((tk + 255) / 256), 256>>>(k, NKV);
    }

    // attention (round-3 FFMA versions)
    intra_kernel<<<dim3(NC, NH), 256, SMEM_BIG>>>();
    recur_kernel<<<(NH * HD * HD + 1023) / 1024, 1024>>>();
    inter_kernel<<<dim3(NC, NH), 256, SMEM_BIG>>>(gnorm);

    // output projection
    gemm_big<<<dim3(HIDDEN / 256, LSEQ / 128), 512, SMEM_GEMM>>>(y, Wo, out, LSEQ, HIDDEN, QDIM);
}